// round 4
// baseline (speedup 1.0000x reference)
#include <cuda_runtime.h>
#include <cstdint>

#define NN   100000
#define EE   1600000
#define BB   512
#define EPN  200000
#define NINK 64
#define HID  72
#define EPSBN 1e-5f

// ---------------- scratch (device globals: no allocation allowed) ----------------
__device__ __align__(16) float    g_deg[NN];
__device__ __align__(16) float    g_norm[EE];
__device__ __align__(16) float    g_h[NN * HID];     // node features (pre/post layer)
__device__ __align__(16) float    g_t[NN * HID];     // h @ Wi
__device__ __align__(16) float    g_acc[NN * HID];   // h @ Wr + bias, then += scatter
__device__ __align__(16) float    g_e[NN * HID];     // relu(emb @ emb_w + b)
__device__ __align__(16) float    g_sum[HID];
__device__ __align__(16) float    g_sq[HID];
__device__ __align__(16) float    g_scale[HID];
__device__ __align__(16) float    g_shift[HID];
__device__ __align__(16) float    g_p1[BB * 2 * HID];
__device__ __align__(16) unsigned g_p2[BB * 2 * HID];
__device__ __align__(16) float    g_cnt[BB];
__device__ __align__(16) float    g_Ya[BB * HID];
__device__ __align__(16) float    g_Yb[BB * HID];

// order-preserving float<->uint encoding for atomicMax on floats (incl. negatives)
__device__ __forceinline__ unsigned fenc(float f) {
    unsigned u = __float_as_uint(f);
    return (u & 0x80000000u) ? ~u : (u | 0x80000000u);
}
__device__ __forceinline__ float fdec(unsigned u) {
    return (u & 0x80000000u) ? __uint_as_float(u ^ 0x80000000u) : __uint_as_float(~u);
}
#define ENC_NEG_INF 0x007FFFFFu   // fenc(-inf)

// ---------------- resets (reference device symbols directly) ----------------
__global__ void reset_deg() {
    int i = blockIdx.x * blockDim.x + threadIdx.x;
    if (i < NN) g_deg[i] = 0.f;
}
__global__ void reset_bnstats() {
    int i = threadIdx.x;
    if (i < HID) { g_sum[i] = 0.f; g_sq[i] = 0.f; }
}
__global__ void reset_pool() {
    int i = blockIdx.x * blockDim.x + threadIdx.x;
    if (i < BB * 2 * HID) { g_p1[i] = 0.f; g_p2[i] = ENC_NEG_INF; }
    if (i < BB) g_cnt[i] = 0.f;
}

// ---------------- degree / norm (edge_index is INT32: JAX x64 disabled) ----------
__global__ void degree_kernel(const int* __restrict__ eidx) {
    int i = blockIdx.x * blockDim.x + threadIdx.x;
    if (i < EE) atomicAdd(&g_deg[eidx[EE + i]], 1.0f);
}
__global__ void norm_kernel(const int* __restrict__ eidx) {
    int i = blockIdx.x * blockDim.x + threadIdx.x;
    if (i >= EE) return;
    float dr = g_deg[eidx[i]];
    float dc = g_deg[eidx[EE + i]];
    float a = dr > 0.f ? rsqrtf(dr) : 0.f;
    float b = dc > 0.f ? rsqrtf(dc) : 0.f;
    g_norm[i] = a * b;
}

// ---------------- input GEMM: dst = relu(in[N,K] @ W[K,72] + bias) ----------------
template <int K, int DST>
__global__ void gemm_in_relu(const float* __restrict__ in, const float* __restrict__ W,
                             const float* __restrict__ bias) {
    float* __restrict__ out = (DST == 0) ? g_h : g_e;
    const int ROWS = 64;
    __shared__ float s_in[ROWS * (K + 1)];
    __shared__ float s_w[K * HID];
    int row0 = blockIdx.x * ROWS;
    for (int idx = threadIdx.x; idx < ROWS * K; idx += 64) {
        int g = row0 * K + idx;
        float v = (g < NN * K) ? in[g] : 0.f;
        s_in[(idx / K) * (K + 1) + (idx % K)] = v;
    }
    for (int idx = threadIdx.x; idx < K * HID; idx += 64) s_w[idx] = W[idx];
    __syncthreads();
    float acc[HID];
#pragma unroll
    for (int j = 0; j < HID; j++) acc[j] = bias[j];
    for (int k = 0; k < K; k++) {
        float a = s_in[threadIdx.x * (K + 1) + k];
#pragma unroll
        for (int j = 0; j < HID; j++) acc[j] += a * s_w[k * HID + j];
    }
    int row = row0 + threadIdx.x;
    if (row < NN) {
        float4* o = reinterpret_cast<float4*>(out + row * HID);
#pragma unroll
        for (int j = 0; j < HID; j += 4)
            o[j / 4] = make_float4(fmaxf(acc[j], 0.f), fmaxf(acc[j + 1], 0.f),
                                   fmaxf(acc[j + 2], 0.f), fmaxf(acc[j + 3], 0.f));
    }
}

// ---------------- conv layer GEMMs: t = h@Wi ; acc = h@Wr + bias ----------------
template <bool BN>
__global__ void conv_gemm(const float* __restrict__ Wi, const float* __restrict__ Wr,
                          const float* __restrict__ bias) {
    const int ROWS = 64;
    const int K = HID;
    __shared__ float s_in[ROWS * (K + 1)];
    __shared__ float s_w[K * HID];
    int row0 = blockIdx.x * ROWS;
    for (int idx = threadIdx.x; idx < ROWS * K; idx += 64) {
        int g = row0 * K + idx;
        float v = (g < NN * K) ? g_h[g] : 0.f;
        if (BN) { int c = idx % K; v = v * g_scale[c] + g_shift[c]; }
        s_in[(idx / K) * (K + 1) + (idx % K)] = v;
    }
    for (int idx = threadIdx.x; idx < K * HID; idx += 64) s_w[idx] = Wi[idx];
    __syncthreads();
    int row = row0 + threadIdx.x;
    float acc[HID];
#pragma unroll
    for (int j = 0; j < HID; j++) acc[j] = 0.f;
    for (int k = 0; k < K; k++) {
        float a = s_in[threadIdx.x * (K + 1) + k];
#pragma unroll
        for (int j = 0; j < HID; j++) acc[j] += a * s_w[k * HID + j];
    }
    if (row < NN) {
        float4* o = reinterpret_cast<float4*>(g_t + row * HID);
#pragma unroll
        for (int j = 0; j < HID; j += 4)
            o[j / 4] = make_float4(acc[j], acc[j + 1], acc[j + 2], acc[j + 3]);
    }
    __syncthreads();
    for (int idx = threadIdx.x; idx < K * HID; idx += 64) s_w[idx] = Wr[idx];
    __syncthreads();
#pragma unroll
    for (int j = 0; j < HID; j++) acc[j] = bias[j];
    for (int k = 0; k < K; k++) {
        float a = s_in[threadIdx.x * (K + 1) + k];
#pragma unroll
        for (int j = 0; j < HID; j++) acc[j] += a * s_w[k * HID + j];
    }
    if (row < NN) {
        float4* o = reinterpret_cast<float4*>(g_acc + row * HID);
#pragma unroll
        for (int j = 0; j < HID; j += 4)
            o[j / 4] = make_float4(acc[j], acc[j + 1], acc[j + 2], acc[j + 3]);
    }
}

// ---------------- edge scatter: acc[col] += norm * t[row] ----------------
__global__ void scatter_edges(const int* __restrict__ eidx) {
    int idx = blockIdx.x * blockDim.x + threadIdx.x;   // EE*18 = 28.8M exact
    int e = idx / 18;
    int ch = idx - e * 18;
    if (e >= EE) return;
    int r = eidx[e];
    int c = eidx[EE + e];
    float nrm = g_norm[e];
    float4 v = *reinterpret_cast<const float4*>(g_t + r * HID + ch * 4);
    float* p = g_acc + c * HID + ch * 4;
    atomicAdd(p + 0, v.x * nrm);
    atomicAdd(p + 1, v.y * nrm);
    atomicAdd(p + 2, v.z * nrm);
    atomicAdd(p + 3, v.w * nrm);
}

// ---------------- batchnorm: stats over relu(acc); h <- relu(acc) ----------------
__global__ void bn_stats() {
    __shared__ float s_sum[HID], s_sq[HID];
    if (threadIdx.x < HID) { s_sum[threadIdx.x] = 0.f; s_sq[threadIdx.x] = 0.f; }
    __syncthreads();
    for (int i = blockIdx.x * blockDim.x + threadIdx.x; i < NN * HID;
         i += gridDim.x * blockDim.x) {
        float v = fmaxf(g_acc[i], 0.f);
        g_h[i] = v;
        int c = i % HID;
        atomicAdd(&s_sum[c], v);
        atomicAdd(&s_sq[c], v * v);
    }
    __syncthreads();
    if (threadIdx.x < HID) {
        atomicAdd(&g_sum[threadIdx.x], s_sum[threadIdx.x]);
        atomicAdd(&g_sq[threadIdx.x], s_sq[threadIdx.x]);
    }
}
__global__ void bn_finalize(const float* __restrict__ gamma, const float* __restrict__ beta) {
    int c = threadIdx.x;
    if (c >= HID) return;
    float mu = g_sum[c] * (1.0f / NN);
    float var = g_sq[c] * (1.0f / NN) - mu * mu;
    float inv = rsqrtf(var + EPSBN);
    float sc = inv * gamma[c];
    g_scale[c] = sc;
    g_shift[c] = beta[c] - mu * sc;
}
__global__ void bn_apply() {
    int i = blockIdx.x * blockDim.x + threadIdx.x;
    if (i < NN * HID) {
        int c = i % HID;
        g_h[i] = g_h[i] * g_scale[c] + g_shift[c];
    }
}

// ---------------- pooling: argmax(assign) + segment sum/max/cnt ----------------
__global__ void pool_kernel(const float* __restrict__ assign) {
    int w = (blockIdx.x * blockDim.x + threadIdx.x) >> 5;
    int lane = threadIdx.x & 31;
    if (w >= NN) return;
    const float* a = assign + (size_t)w * BB;
    float best = -__int_as_float(0x7f800000);  // -inf
    int bi = 0x7fffffff;
    for (int j = lane; j < BB; j += 32) {
        float v = a[j];
        if (v > best) { best = v; bi = j; }
    }
#pragma unroll
    for (int off = 16; off; off >>= 1) {
        float ov = __shfl_xor_sync(0xffffffffu, best, off);
        int oi = __shfl_xor_sync(0xffffffffu, bi, off);
        if (ov > best || (ov == best && oi < bi)) { best = ov; bi = oi; }
    }
    int b = bi;
    for (int c = lane; c < 2 * HID; c += 32) {
        float zv = (c < HID) ? g_h[w * HID + c] : g_e[w * HID + (c - HID)];
        atomicAdd(&g_p1[b * (2 * HID) + c], zv);
        atomicMax(&g_p2[b * (2 * HID) + c], fenc(zv));
    }
    if (lane == 0) atomicAdd(&g_cnt[b], 1.0f);
}

// ---------------- xp build + factored pair-MLP first layer ----------------
// Ya = xp @ W1[0:432] + b1 ; Yb = xp @ W1[432:864]
__global__ void xp_kernel(const float* __restrict__ w1, const float* __restrict__ b1) {
    __shared__ float s_xp[6 * HID];  // 432
    int b = blockIdx.x;
    int t = threadIdx.x;  // 144 threads
    float cnt = g_cnt[b];
    float p1v = g_p1[b * 144 + t];
    s_xp[t] = p1v;
    s_xp[144 + t] = fdec(g_p2[b * 144 + t]);
    s_xp[288 + t] = p1v / fmaxf(cnt, 1.0f);
    __syncthreads();
    int j = (t < HID) ? t : t - HID;
    const float* w = (t < HID) ? w1 : (w1 + 6 * HID * HID);
    float acc = (t < HID) ? b1[j] : 0.f;
    for (int k = 0; k < 6 * HID; k++) acc += s_xp[k] * w[k * HID + j];
    if (t < HID) g_Ya[b * HID + j] = acc;
    else         g_Yb[b * HID + j] = acc;
}

// ---------------- pair output: out = tanh(Ya[p0]+Yb[p1]) . w2 + b2 ----------------
__global__ void pair_kernel(const int* __restrict__ pe, const float* __restrict__ w2,
                            const float* __restrict__ b2, float* __restrict__ out) {
    int w = (blockIdx.x * blockDim.x + threadIdx.x) >> 5;
    int lane = threadIdx.x & 31;
    if (w >= EPN) return;
    int a = pe[w];
    int b = pe[EPN + w];
    float acc = 0.f;
    for (int c = lane; c < HID; c += 32) {
        float v = g_Ya[a * HID + c] + g_Yb[b * HID + c];
        acc += tanhf(v) * w2[c];
    }
#pragma unroll
    for (int off = 16; off; off >>= 1) acc += __shfl_xor_sync(0xffffffffu, acc, off);
    if (lane == 0) out[w] = acc + b2[0];
}

// ---------------- launch: kernel launches ONLY ----------------
extern "C" void kernel_launch(void* const* d_in, const int* in_sizes, int n_in,
                              void* d_out, int out_size) {
    const float* x         = (const float*)d_in[0];
    const float* emb       = (const float*)d_in[1];
    const float* assign    = (const float*)d_in[2];
    const int*   eidx      = (const int*)d_in[3];    // int32 (JAX x64 disabled)
    const int*   pedge     = (const int*)d_in[4];    // int32
    const float* node_w    = (const float*)d_in[5];
    const float* node_b    = (const float*)d_in[6];
    const float* emb_w     = (const float*)d_in[7];
    const float* emb_b     = (const float*)d_in[8];
    const float* conv_wi   = (const float*)d_in[9];
    const float* conv_wr   = (const float*)d_in[10];
    const float* conv_bias = (const float*)d_in[11];
    const float* bn_gamma  = (const float*)d_in[12];
    const float* bn_beta   = (const float*)d_in[13];
    const float* mlp_w1    = (const float*)d_in[14];
    const float* mlp_b1    = (const float*)d_in[15];
    const float* mlp_w2    = (const float*)d_in[16];
    const float* mlp_b2    = (const float*)d_in[17];
    float*       out       = (float*)d_out;

    // degree + norm
    reset_deg<<<(NN + 255) / 256, 256>>>();
    degree_kernel<<<EE / 256, 256>>>(eidx);
    norm_kernel<<<EE / 256, 256>>>(eidx);

    // input GEMMs (h and e)
    const int GB = (NN + 63) / 64;
    gemm_in_relu<NINK, 0><<<GB, 64>>>(x, node_w, node_b);
    gemm_in_relu<NINK, 1><<<GB, 64>>>(emb, emb_w, emb_b);

    // 3 ARMA conv layers
    for (int l = 0; l < 3; l++) {
        if (l == 0)
            conv_gemm<false><<<GB, 64>>>(conv_wi + l * HID * HID, conv_wr + l * HID * HID,
                                         conv_bias + l * HID);
        else
            conv_gemm<true><<<GB, 64>>>(conv_wi + l * HID * HID, conv_wr + l * HID * HID,
                                        conv_bias + l * HID);
        scatter_edges<<<(EE * 18) / 256, 256>>>(eidx);
        reset_bnstats<<<1, 128>>>();
        bn_stats<<<2048, 256>>>();
        bn_finalize<<<1, 128>>>(bn_gamma + l * HID, bn_beta + l * HID);
    }
    bn_apply<<<(NN * HID + 255) / 256, 256>>>();  // apply last layer's BN to h

    // pooling
    reset_pool<<<(BB * 2 * HID + 255) / 256, 256>>>();
    pool_kernel<<<(NN * 32 + 255) / 256, 256>>>(assign);

    // factored pair MLP
    xp_kernel<<<BB, 144>>>(mlp_w1, mlp_b1);
    pair_kernel<<<(EPN * 32 + 255) / 256, 256>>>(pedge, mlp_w2, mlp_b2, out);
}